// round 14
// baseline (speedup 1.0000x reference)
#include <cuda_runtime.h>
#include <cuda_fp16.h>
#include <cstdint>

#define NN 50000
#define NE 800000
#define NH 4
#define DI 256
#define DO 64
#define CO 256   // NH * DO

#define NB_SCAN 196  // ceil(NN/256)

// ---- scratch (device globals; no runtime allocation) ----
__device__ __half g_featsh[NN * CO];     // [n][h*64+o] fp16
__device__ float4 g_as4[NN];
__device__ float4 g_ad4[NN];
__device__ float g_w[NE * NH];           // CSR-ordered weights [pos][h]
__device__ int   g_rank[NE];             // rank of edge within its src bucket
__device__ int   g_cdst[NE];
__device__ int   g_deg[NN];
__device__ int   g_rowstart[NN + 1];
__device__ float g_bcat[CO];
__device__ int   g_stat[NB_SCAN];        // lookback status: (val<<2)|flag
__device__ float g_v[8 * DI];
__device__ float g_c[8];
__device__ __half g_Bh[CO * DI];         // Bt[n][k] fp16  (n = h*64+o, k = d)

// ==================== small prep kernels ====================
__global__ void prep_kernel(const float* __restrict__ bs) {
    int i = blockIdx.x * blockDim.x + threadIdx.x;
    if (i < CO) {
        int h = i >> 6, o = i & 63;
        g_bcat[i] = bs[h * DO + o];
    }
}

// B transposed fp16: Bt[n][k] = Ws[h][k][o], n = h*64+o
__global__ void prepB_kernel(const float* __restrict__ Ws) {
    int i = blockIdx.x * blockDim.x + threadIdx.x;
    if (i >= CO * DI) return;
    int n = i >> 8, k = i & 255;
    int h = n >> 6, o = n & 63;
    g_Bh[i] = __float2half(Ws[(h * DI + k) * DO + o]);
}

// fused: v/c dot products + deg zeroing + scan-status zeroing
__global__ void prepv_zero_kernel(const float* __restrict__ Ws, const float* __restrict__ bs,
                                  const float* __restrict__ aw) {
    int id = blockIdx.x * blockDim.x + threadIdx.x;
    if (id < 8 * DI) {
        int j = id >> 8, d = id & 255;
        int h = j >> 1, sd = j & 1;
        const float* wrow = Ws + (h * DI + d) * DO;
        const float* arow = aw + h * (2 * DO + 1) + sd * DO;
        float s = 0.f;
#pragma unroll
        for (int o = 0; o < DO; o++) s += wrow[o] * arow[o];
        g_v[id] = s;
    } else if (id < 8 * DI + 8) {
        int j = id - 8 * DI;
        int h = j >> 1, sd = j & 1;
        const float* arow = aw + h * (2 * DO + 1) + sd * DO;
        float s = 0.f;
#pragma unroll
        for (int o = 0; o < DO; o++) s += bs[h * DO + o] * arow[o];
        g_c[j] = s;
    }
    if (id < NN) g_deg[id] = 0;
    if (id < NB_SCAN) g_stat[id] = 0;
}

// count + capture per-edge rank (atomicAdd return value)
__global__ void count_kernel(const int* __restrict__ idx) {
    int e = blockIdx.x * blockDim.x + threadIdx.x;
    if (e < NE) g_rank[e] = atomicAdd(&g_deg[idx[e]], 1);
}

// ---------------- single-kernel decoupled-lookback exclusive scan ----------------
// 196 blocks, all co-resident on 148 SMs -> lookback is deadlock-free.
__global__ void __launch_bounds__(256) scan_lb_kernel() {
    __shared__ int warp_tot[8];
    __shared__ int s_prefix;
    int tid = threadIdx.x;
    int b = blockIdx.x;
    int lane = tid & 31, wid = tid >> 5;
    int i = b * 256 + tid;
    int v = (i < NN) ? g_deg[i] : 0;

    // inclusive warp scan
    int x = v;
#pragma unroll
    for (int off = 1; off < 32; off <<= 1) {
        int t = __shfl_up_sync(0xffffffffu, x, off);
        if (lane >= off) x += t;
    }
    if (lane == 31) warp_tot[wid] = x;
    __syncthreads();
    if (wid == 0) {
        int wt = (lane < 8) ? warp_tot[lane] : 0;
#pragma unroll
        for (int off = 1; off < 8; off <<= 1) {
            int t = __shfl_up_sync(0xffffffffu, wt, off);
            if (lane >= off) wt += t;
        }
        if (lane < 8) warp_tot[lane] = wt;
    }
    __syncthreads();
    int incl = x + (wid ? warp_tot[wid - 1] : 0);
    int btot = warp_tot[7];

    if (tid == 0) {
        if (b == 0) {
            atomicExch(&g_stat[0], (btot << 2) | 2);   // inclusive prefix published
            s_prefix = 0;
        } else {
            atomicExch(&g_stat[b], (btot << 2) | 1);   // aggregate published
            int ex = 0;
            int pb = b - 1;
            while (true) {
                int s = atomicAdd(&g_stat[pb], 0);
                int fl = s & 3;
                if (fl == 0) continue;       // not yet published; spin
                ex += s >> 2;
                if (fl == 2) break;          // hit an inclusive prefix
                pb--;
            }
            s_prefix = ex;
            atomicExch(&g_stat[b], ((ex + btot) << 2) | 2);
        }
    }
    __syncthreads();
    int base = s_prefix;
    if (i < NN) g_rowstart[i] = base + incl - v;
    if (b == NB_SCAN - 1 && tid == 0) g_rowstart[NN] = base + btot;
}

// ---------------- a_s/a_d directly from x: warp per node ----------------
__global__ void __launch_bounds__(256) as_kernel(const float* __restrict__ x) {
    int gw = (blockIdx.x * blockDim.x + threadIdx.x) >> 5;
    int lane = threadIdx.x & 31;
    if (gw >= NN) return;
    const float* xr = x + (size_t)gw * DI;
    float a[8] = {};
#pragma unroll
    for (int c8 = 0; c8 < 8; c8++) {
        float xv = xr[c8 * 32 + lane];
#pragma unroll
        for (int j = 0; j < 8; j++)
            a[j] += xv * __ldg(&g_v[j * DI + c8 * 32 + lane]);
    }
#pragma unroll
    for (int j = 0; j < 8; j++) {
#pragma unroll
        for (int off = 16; off; off >>= 1)
            a[j] += __shfl_xor_sync(0xffffffffu, a[j], off);
    }
    if (lane == 0) {
        g_as4[gw] = make_float4(a[0] + g_c[0], a[2] + g_c[2],
                                a[4] + g_c[4], a[6] + g_c[6]);
        g_ad4[gw] = make_float4(a[1] + g_c[1], a[3] + g_c[3],
                                a[5] + g_c[5], a[7] + g_c[7]);
    }
}

// ==================== warp-level fp16 MMA GEMM (single pass) ====================
#define KS 32          // k-chunk
#define LDA 40         // smem row stride in half elements

__device__ __forceinline__ void mma_f16(float* c, const uint32_t* a, const uint32_t* b) {
    asm volatile(
        "mma.sync.aligned.m16n8k16.row.col.f32.f16.f16.f32 "
        "{%0,%1,%2,%3}, {%4,%5,%6,%7}, {%8,%9}, {%0,%1,%2,%3};"
        : "+f"(c[0]), "+f"(c[1]), "+f"(c[2]), "+f"(c[3])
        : "r"(a[0]), "r"(a[1]), "r"(a[2]), "r"(a[3]), "r"(b[0]), "r"(b[1]));
}

__global__ void __launch_bounds__(256, 2) gemm_mma_kernel(const float* __restrict__ x) {
    __shared__ __align__(16) __half sAh[128 * LDA];
    __shared__ __align__(16) __half sBh[128 * LDA];

    int tid = threadIdx.x;
    int wid = tid >> 5;
    int lane = tid & 31;
    int group = lane >> 2;
    int tid4 = lane & 3;
    int bm = blockIdx.y * 128;
    int bn = blockIdx.x * 128;
    int wm = (wid & 3) * 32;
    int wn = (wid >> 2) * 64;

    int lrow = tid >> 1;
    int lk0 = (tid & 1) * 16;
    int grow = bm + lrow;
    bool aok = grow < NN;
    const float4* xp = (const float4*)(x + (size_t)grow * DI);
    const uint4* bhp = (const uint4*)(g_Bh + (size_t)(bn + lrow) * DI);

    float acc[2][8][4] = {};

    for (int c = 0; c < DI / KS; c++) {
        if (c) __syncthreads();
        int ck = c * KS;
#pragma unroll
        for (int q = 0; q < 4; q++) {
            float4 v = aok ? __ldg(xp + ((ck + lk0) >> 2) + q)
                           : make_float4(0.f, 0.f, 0.f, 0.f);
            __half2 h01 = __floats2half2_rn(v.x, v.y);
            __half2 h23 = __floats2half2_rn(v.z, v.w);
            int e = lrow * LDA + lk0 + q * 4;
            *(__half2*)&sAh[e]     = h01;
            *(__half2*)&sAh[e + 2] = h23;
        }
        {
            uint4 v0 = __ldg(bhp + ((ck + lk0) >> 3));
            uint4 v1 = __ldg(bhp + ((ck + lk0) >> 3) + 1);
            int e = lrow * LDA + lk0;
            *(uint4*)&sBh[e]     = v0;
            *(uint4*)&sBh[e + 8] = v1;
        }
        __syncthreads();

#pragma unroll
        for (int k16 = 0; k16 < KS; k16 += 16) {
            uint32_t ah[2][4];
#pragma unroll
            for (int mi = 0; mi < 2; mi++) {
                int r0 = (wm + mi * 16 + group) * LDA + k16 + tid4 * 2;
                ah[mi][0] = *(const uint32_t*)&sAh[r0];
                ah[mi][1] = *(const uint32_t*)&sAh[r0 + 8 * LDA];
                ah[mi][2] = *(const uint32_t*)&sAh[r0 + 8];
                ah[mi][3] = *(const uint32_t*)&sAh[r0 + 8 * LDA + 8];
            }
#pragma unroll
            for (int ni = 0; ni < 8; ni++) {
                int rb = (wn + ni * 8 + group) * LDA + k16 + tid4 * 2;
                uint32_t bh[2];
                bh[0] = *(const uint32_t*)&sBh[rb];
                bh[1] = *(const uint32_t*)&sBh[rb + 8];
#pragma unroll
                for (int mi = 0; mi < 2; mi++)
                    mma_f16(acc[mi][ni], ah[mi], bh);
            }
        }
    }

    // epilogue: add bias, store fp16
#pragma unroll
    for (int mi = 0; mi < 2; mi++) {
        int row0 = bm + wm + mi * 16 + group;
        int row1 = row0 + 8;
#pragma unroll
        for (int ni = 0; ni < 8; ni++) {
            int col = bn + wn + ni * 8 + tid4 * 2;
            float2 bb = *(const float2*)(g_bcat + col);
            if (row0 < NN) {
                __half2 o0 = __floats2half2_rn(acc[mi][ni][0] + bb.x, acc[mi][ni][1] + bb.y);
                *(__half2*)(g_featsh + (size_t)row0 * CO + col) = o0;
            }
            if (row1 < NN) {
                __half2 o1 = __floats2half2_rn(acc[mi][ni][2] + bb.x, acc[mi][ni][3] + bb.y);
                *(__half2*)(g_featsh + (size_t)row1 * CO + col) = o1;
            }
        }
    }
}

// ---------------- fused: edge weights + CSR placement (no atomics, no intermediate) ----------------
__global__ void place_kernel(const int* __restrict__ idx, const float* __restrict__ elem,
                             const float* __restrict__ aw, const float* __restrict__ ab) {
    int e = blockIdx.x * blockDim.x + threadIdx.x;
    if (e >= NE) return;
    int s = idx[e];
    int d = idx[NE + e];
    float el = elem[e];
    float4 as = __ldg(&g_as4[s]);
    float4 ad = __ldg(&g_ad4[d]);
    const float* asv = (const float*)&as;
    const float* adv = (const float*)&ad;
    float w[NH];
#pragma unroll
    for (int h = 0; h < NH; h++) {
        float sc = asv[h] + adv[h]
                 + __ldg(&aw[h * (2 * DO + 1) + 2 * DO]) * el + __ldg(&ab[h]);
        sc = sc * (1.0f / 20.0f);
        w[h] = __expf(-fmaxf(sc, 0.0f));
    }
    int pos = g_rowstart[s] + g_rank[e];
    g_cdst[pos] = d;
    *(float4*)(g_w + (size_t)pos * 4) = make_float4(w[0], w[1], w[2], w[3]);
}

// ---------------- per-node gather + normalize (32 thr/node, 8 nodes/block) ----------------
__global__ void __launch_bounds__(256) gather_kernel(float* __restrict__ out) {
    int t = threadIdx.x;
    int n = blockIdx.x * 8 + (t >> 5);
    int l = t & 31;              // lane handles elements l*8 .. l*8+7
    int h = l >> 3;              // head index = (l*8)/64
    int start = g_rowstart[n];
    int end = g_rowstart[n + 1];

    const uint4* fp = (const uint4*)g_featsh;   // 32 uint4 per row (256 half)
    float acc[8] = {};
    float wsum = 0.f;

    int j = start;
    for (; j + 4 <= end; j += 4) {
        int d0 = __ldg(&g_cdst[j + 0]);
        int d1 = __ldg(&g_cdst[j + 1]);
        int d2 = __ldg(&g_cdst[j + 2]);
        int d3 = __ldg(&g_cdst[j + 3]);
        float w0 = __ldg(&g_w[(size_t)(j + 0) * 4 + h]);
        float w1 = __ldg(&g_w[(size_t)(j + 1) * 4 + h]);
        float w2 = __ldg(&g_w[(size_t)(j + 2) * 4 + h]);
        float w3 = __ldg(&g_w[(size_t)(j + 3) * 4 + h]);
        uint4 f0 = __ldg(fp + (size_t)d0 * 32 + l);
        uint4 f1 = __ldg(fp + (size_t)d1 * 32 + l);
        uint4 f2 = __ldg(fp + (size_t)d2 * 32 + l);
        uint4 f3 = __ldg(fp + (size_t)d3 * 32 + l);

#define ACCUM(F, W) do {                                              \
        float2 p0 = __half22float2(*(const __half2*)&(F).x);          \
        float2 p1 = __half22float2(*(((const __half2*)&(F).x) + 1));  \
        float2 p2 = __half22float2(*(const __half2*)&(F).z);          \
        float2 p3 = __half22float2(*(((const __half2*)&(F).z) + 1));  \
        acc[0] += (W) * p0.x;  acc[1] += (W) * p0.y;                  \
        acc[2] += (W) * p1.x;  acc[3] += (W) * p1.y;                  \
        acc[4] += (W) * p2.x;  acc[5] += (W) * p2.y;                  \
        acc[6] += (W) * p3.x;  acc[7] += (W) * p3.y;                  \
        wsum += (W);                                                  \
    } while (0)

        ACCUM(f0, w0);
        ACCUM(f1, w1);
        ACCUM(f2, w2);
        ACCUM(f3, w3);
    }
    for (; j < end; j++) {
        int dst = __ldg(&g_cdst[j]);
        float w = __ldg(&g_w[(size_t)j * 4 + h]);
        uint4 f = __ldg(fp + (size_t)dst * 32 + l);
        ACCUM(f, w);
    }
#undef ACCUM

    float inv = 1.0f / wsum;     // 0 edges -> inf -> 0*inf = NaN, matching reference
    float4 o0 = make_float4(acc[0] * inv, acc[1] * inv, acc[2] * inv, acc[3] * inv);
    float4 o1 = make_float4(acc[4] * inv, acc[5] * inv, acc[6] * inv, acc[7] * inv);
    float* op = out + (size_t)n * CO + l * 8;
    *(float4*)(op)     = o0;
    *(float4*)(op + 4) = o1;
}

extern "C" void kernel_launch(void* const* d_in, const int* in_sizes, int n_in,
                              void* d_out, int out_size) {
    const float* x    = (const float*)d_in[0];
    const int*   idx  = (const int*)d_in[1];
    const float* elem = (const float*)d_in[2];
    const float* Ws   = (const float*)d_in[3];
    const float* bs   = (const float*)d_in[4];
    const float* aw   = (const float*)d_in[5];
    const float* ab   = (const float*)d_in[6];
    float* out = (float*)d_out;

    static cudaStream_t s1 = nullptr, s2 = nullptr;
    static cudaEvent_t evF = nullptr, evPv = nullptr, evAs = nullptr, evJ = nullptr;
    if (!s1) {   // created on the (uncaptured) correctness call, reused thereafter
        cudaStreamCreateWithFlags(&s1, cudaStreamNonBlocking);
        cudaStreamCreateWithFlags(&s2, cudaStreamNonBlocking);
        cudaEventCreateWithFlags(&evF, cudaEventDisableTiming);
        cudaEventCreateWithFlags(&evPv, cudaEventDisableTiming);
        cudaEventCreateWithFlags(&evAs, cudaEventDisableTiming);
        cudaEventCreateWithFlags(&evJ, cudaEventDisableTiming);
    }

    // fork from origin (legacy) stream
    cudaEventRecord(evF, 0);
    cudaStreamWaitEvent(s1, evF, 0);

    // s1: fused prepv + deg/status zero
    prepv_zero_kernel<<<(NN + 255) / 256, 256, 0, s1>>>(Ws, bs, aw);
    cudaEventRecord(evPv, s1);

    // legacy: GEMM prep
    prep_kernel<<<1, 256>>>(bs);
    prepB_kernel<<<(CO * DI + 255) / 256, 256>>>(Ws);

    // s1: count (+rank) then single-kernel scan
    count_kernel<<<(NE + 255) / 256, 256, 0, s1>>>(idx);
    scan_lb_kernel<<<NB_SCAN, 256, 0, s1>>>();

    // legacy: GEMM
    gemm_mma_kernel<<<dim3(2, (NN + 127) / 128), 256>>>(x);

    // s2: attention dots (needs only prepv; overlaps count/scan)
    cudaStreamWaitEvent(s2, evPv, 0);
    as_kernel<<<(NN * 32 + 255) / 256, 256, 0, s2>>>(x);
    cudaEventRecord(evAs, s2);

    // s1: fused place needs scan (same stream) + as (cross-stream); no atomics
    cudaStreamWaitEvent(s1, evAs, 0);
    place_kernel<<<(NE + 255) / 256, 256, 0, s1>>>(idx, elem, aw, ab);
    cudaEventRecord(evJ, s1);

    // join, then gather (needs feats + CSR + weights)
    cudaStreamWaitEvent(0, evJ, 0);
    gather_kernel<<<(NN + 7) / 8, 256>>>(out);
}

// round 15
// speedup vs baseline: 1.1123x; 1.1123x over previous
#include <cuda_runtime.h>
#include <cuda_fp16.h>
#include <cstdint>

#define NN 50000
#define NE 800000
#define NH 4
#define DI 256
#define DO 64
#define CO 256   // NH * DO

#define NB_SCAN 196  // ceil(NN/256)

// ---- scratch (device globals; no runtime allocation) ----
__device__ __half g_featsh[NN * CO];     // [n][h*64+o] fp16
__device__ float g_as[NN * NH];          // per-node src dots (written by gemm epilogue)
__device__ float g_ad[NN * NH];          // per-node dst dots
__device__ float g_w[NE * NH];           // CSR-ordered weights [pos][h]
__device__ int   g_rank[NE];             // rank of edge within its src bucket
__device__ int   g_cdst[NE];
__device__ int   g_deg[NN];
__device__ int   g_rowstart[NN + 1];
__device__ float g_bcat[CO];
__device__ int   g_part[NB_SCAN];
__device__ __half g_Bh[CO * DI];         // Bt[n][k] fp16  (n = h*64+o, k = d)

// ==================== small prep kernels ====================
__global__ void prep_kernel(const float* __restrict__ bs) {
    int i = blockIdx.x * blockDim.x + threadIdx.x;
    if (i < CO) {
        int h = i >> 6, o = i & 63;
        g_bcat[i] = bs[h * DO + o];
    }
}

// B transposed fp16: Bt[n][k] = Ws[h][k][o], n = h*64+o
__global__ void prepB_kernel(const float* __restrict__ Ws) {
    int i = blockIdx.x * blockDim.x + threadIdx.x;
    if (i >= CO * DI) return;
    int n = i >> 8, k = i & 255;
    int h = n >> 6, o = n & 63;
    g_Bh[i] = __float2half(Ws[(h * DI + k) * DO + o]);
}

// deg zeroing only (v/c precompute no longer needed)
__global__ void zero_kernel() {
    int id = blockIdx.x * blockDim.x + threadIdx.x;
    if (id < NN) g_deg[id] = 0;
}

// count + capture per-edge rank (atomicAdd return value)
__global__ void count_kernel(const int* __restrict__ idx) {
    int e = blockIdx.x * blockDim.x + threadIdx.x;
    if (e < NE) g_rank[e] = atomicAdd(&g_deg[idx[e]], 1);
}

// ---------------- 3-phase decoupled scan ----------------
__global__ void scan1_kernel() {
    __shared__ int sd[256];
    int tid = threadIdx.x;
    int i = blockIdx.x * 256 + tid;
    sd[tid] = (i < NN) ? g_deg[i] : 0;
    __syncthreads();
    for (int off = 128; off; off >>= 1) {
        if (tid < off) sd[tid] += sd[tid + off];
        __syncthreads();
    }
    if (tid == 0) g_part[blockIdx.x] = sd[0];
}

__global__ void scan2_kernel() {
    __shared__ int sd[256];
    int tid = threadIdx.x;
    int v = (tid < NB_SCAN) ? g_part[tid] : 0;
    sd[tid] = v;
    __syncthreads();
    for (int off = 1; off < 256; off <<= 1) {
        int t = (tid >= off) ? sd[tid - off] : 0;
        __syncthreads();
        sd[tid] += t;
        __syncthreads();
    }
    if (tid < NB_SCAN) g_part[tid] = sd[tid] - v;
    if (tid == 255) g_rowstart[NN] = sd[255];
}

__global__ void scan3_kernel() {
    __shared__ int sd[256];
    int tid = threadIdx.x;
    int i = blockIdx.x * 256 + tid;
    int v = (i < NN) ? g_deg[i] : 0;
    sd[tid] = v;
    __syncthreads();
    for (int off = 1; off < 256; off <<= 1) {
        int t = (tid >= off) ? sd[tid - off] : 0;
        __syncthreads();
        sd[tid] += t;
        __syncthreads();
    }
    if (i < NN) g_rowstart[i] = g_part[blockIdx.x] + sd[tid] - v;
}

// ==================== warp-level fp16 MMA GEMM + fused attention dots ====================
#define KS 32          // k-chunk
#define LDA 40         // smem row stride in half elements

__device__ __forceinline__ void mma_f16(float* c, const uint32_t* a, const uint32_t* b) {
    asm volatile(
        "mma.sync.aligned.m16n8k16.row.col.f32.f16.f16.f32 "
        "{%0,%1,%2,%3}, {%4,%5,%6,%7}, {%8,%9}, {%0,%1,%2,%3};"
        : "+f"(c[0]), "+f"(c[1]), "+f"(c[2]), "+f"(c[3])
        : "r"(a[0]), "r"(a[1]), "r"(a[2]), "r"(a[3]), "r"(b[0]), "r"(b[1]));
}

__global__ void __launch_bounds__(256, 2) gemm_mma_kernel(const float* __restrict__ x,
                                                          const float* __restrict__ aw) {
    __shared__ __align__(16) __half sAh[128 * LDA];
    __shared__ __align__(16) __half sBh[128 * LDA];

    int tid = threadIdx.x;
    int wid = tid >> 5;
    int lane = tid & 31;
    int group = lane >> 2;
    int tid4 = lane & 3;
    int bm = blockIdx.y * 128;
    int bn = blockIdx.x * 128;
    int wm = (wid & 3) * 32;
    int wn = (wid >> 2) * 64;

    int lrow = tid >> 1;
    int lk0 = (tid & 1) * 16;
    int grow = bm + lrow;
    bool aok = grow < NN;
    const float4* xp = (const float4*)(x + (size_t)grow * DI);
    const uint4* bhp = (const uint4*)(g_Bh + (size_t)(bn + lrow) * DI);

    float acc[2][8][4] = {};

    for (int c = 0; c < DI / KS; c++) {
        if (c) __syncthreads();
        int ck = c * KS;
#pragma unroll
        for (int q = 0; q < 4; q++) {
            float4 v = aok ? __ldg(xp + ((ck + lk0) >> 2) + q)
                           : make_float4(0.f, 0.f, 0.f, 0.f);
            __half2 h01 = __floats2half2_rn(v.x, v.y);
            __half2 h23 = __floats2half2_rn(v.z, v.w);
            int e = lrow * LDA + lk0 + q * 4;
            *(__half2*)&sAh[e]     = h01;
            *(__half2*)&sAh[e + 2] = h23;
        }
        {
            uint4 v0 = __ldg(bhp + ((ck + lk0) >> 3));
            uint4 v1 = __ldg(bhp + ((ck + lk0) >> 3) + 1);
            int e = lrow * LDA + lk0;
            *(uint4*)&sBh[e]     = v0;
            *(uint4*)&sBh[e + 8] = v1;
        }
        __syncthreads();

#pragma unroll
        for (int k16 = 0; k16 < KS; k16 += 16) {
            uint32_t ah[2][4];
#pragma unroll
            for (int mi = 0; mi < 2; mi++) {
                int r0 = (wm + mi * 16 + group) * LDA + k16 + tid4 * 2;
                ah[mi][0] = *(const uint32_t*)&sAh[r0];
                ah[mi][1] = *(const uint32_t*)&sAh[r0 + 8 * LDA];
                ah[mi][2] = *(const uint32_t*)&sAh[r0 + 8];
                ah[mi][3] = *(const uint32_t*)&sAh[r0 + 8 * LDA + 8];
            }
#pragma unroll
            for (int ni = 0; ni < 8; ni++) {
                int rb = (wn + ni * 8 + group) * LDA + k16 + tid4 * 2;
                uint32_t bh[2];
                bh[0] = *(const uint32_t*)&sBh[rb];
                bh[1] = *(const uint32_t*)&sBh[rb + 8];
#pragma unroll
                for (int mi = 0; mi < 2; mi++)
                    mma_f16(acc[mi][ni], ah[mi], bh);
            }
        }
    }

    // ---- epilogue: bias, fp16 store, fused a_s/a_d dots ----
    // head of this warp's 64-col block (unique (row, head) writer -> plain stores)
    int hh = (bn + wn) >> 6;
    const float* awh = aw + hh * (2 * DO + 1);

    float ps[2][2] = {};   // [mi][r] partial src dots
    float pd[2][2] = {};   // [mi][r] partial dst dots

#pragma unroll
    for (int ni = 0; ni < 8; ni++) {
        int o = ni * 8 + tid4 * 2;          // col within 64-col head block
        int col = bn + wn + o;
        float2 bb = *(const float2*)(g_bcat + col);
        float aws0 = __ldg(&awh[o]);
        float aws1 = __ldg(&awh[o + 1]);
        float awd0 = __ldg(&awh[DO + o]);
        float awd1 = __ldg(&awh[DO + o + 1]);
#pragma unroll
        for (int mi = 0; mi < 2; mi++) {
            int row0 = bm + wm + mi * 16 + group;
            int row1 = row0 + 8;
            float v00 = acc[mi][ni][0] + bb.x;
            float v01 = acc[mi][ni][1] + bb.y;
            float v10 = acc[mi][ni][2] + bb.x;
            float v11 = acc[mi][ni][3] + bb.y;
            ps[mi][0] += v00 * aws0 + v01 * aws1;
            pd[mi][0] += v00 * awd0 + v01 * awd1;
            ps[mi][1] += v10 * aws0 + v11 * aws1;
            pd[mi][1] += v10 * awd0 + v11 * awd1;
            if (row0 < NN)
                *(__half2*)(g_featsh + (size_t)row0 * CO + col) = __floats2half2_rn(v00, v01);
            if (row1 < NN)
                *(__half2*)(g_featsh + (size_t)row1 * CO + col) = __floats2half2_rn(v10, v11);
        }
    }

    // quad reduction over tid4 (lane bits 0-1)
#pragma unroll
    for (int mi = 0; mi < 2; mi++)
#pragma unroll
        for (int r = 0; r < 2; r++) {
            ps[mi][r] += __shfl_xor_sync(0xffffffffu, ps[mi][r], 1);
            ps[mi][r] += __shfl_xor_sync(0xffffffffu, ps[mi][r], 2);
            pd[mi][r] += __shfl_xor_sync(0xffffffffu, pd[mi][r], 1);
            pd[mi][r] += __shfl_xor_sync(0xffffffffu, pd[mi][r], 2);
        }
    if (tid4 == 0) {
#pragma unroll
        for (int mi = 0; mi < 2; mi++)
#pragma unroll
            for (int r = 0; r < 2; r++) {
                int row = bm + wm + mi * 16 + group + r * 8;
                if (row < NN) {
                    g_as[row * NH + hh] = ps[mi][r];
                    g_ad[row * NH + hh] = pd[mi][r];
                }
            }
    }
}

// ---------------- fused: edge weights + CSR placement (no atomics) ----------------
__global__ void place_kernel(const int* __restrict__ idx, const float* __restrict__ elem,
                             const float* __restrict__ aw, const float* __restrict__ ab) {
    int e = blockIdx.x * blockDim.x + threadIdx.x;
    if (e >= NE) return;
    int s = idx[e];
    int d = idx[NE + e];
    float el = elem[e];
    float4 as = *(const float4*)(g_as + s * NH);
    float4 ad = *(const float4*)(g_ad + d * NH);
    const float* asv = (const float*)&as;
    const float* adv = (const float*)&ad;
    float w[NH];
#pragma unroll
    for (int h = 0; h < NH; h++) {
        float sc = asv[h] + adv[h]
                 + __ldg(&aw[h * (2 * DO + 1) + 2 * DO]) * el + __ldg(&ab[h]);
        sc = sc * (1.0f / 20.0f);
        w[h] = __expf(-fmaxf(sc, 0.0f));
    }
    int pos = g_rowstart[s] + g_rank[e];
    g_cdst[pos] = d;
    *(float4*)(g_w + (size_t)pos * 4) = make_float4(w[0], w[1], w[2], w[3]);
}

// ---------------- per-node gather + normalize (32 thr/node, 8 nodes/block) ----------------
__global__ void __launch_bounds__(256) gather_kernel(float* __restrict__ out) {
    int t = threadIdx.x;
    int n = blockIdx.x * 8 + (t >> 5);
    int l = t & 31;              // lane handles elements l*8 .. l*8+7
    int h = l >> 3;              // head index = (l*8)/64
    int start = g_rowstart[n];
    int end = g_rowstart[n + 1];

    const uint4* fp = (const uint4*)g_featsh;   // 32 uint4 per row (256 half)
    float acc[8] = {};
    float wsum = 0.f;

    int j = start;
    for (; j + 4 <= end; j += 4) {
        int d0 = __ldg(&g_cdst[j + 0]);
        int d1 = __ldg(&g_cdst[j + 1]);
        int d2 = __ldg(&g_cdst[j + 2]);
        int d3 = __ldg(&g_cdst[j + 3]);
        float w0 = __ldg(&g_w[(size_t)(j + 0) * 4 + h]);
        float w1 = __ldg(&g_w[(size_t)(j + 1) * 4 + h]);
        float w2 = __ldg(&g_w[(size_t)(j + 2) * 4 + h]);
        float w3 = __ldg(&g_w[(size_t)(j + 3) * 4 + h]);
        uint4 f0 = __ldg(fp + (size_t)d0 * 32 + l);
        uint4 f1 = __ldg(fp + (size_t)d1 * 32 + l);
        uint4 f2 = __ldg(fp + (size_t)d2 * 32 + l);
        uint4 f3 = __ldg(fp + (size_t)d3 * 32 + l);

#define ACCUM(F, W) do {                                              \
        float2 p0 = __half22float2(*(const __half2*)&(F).x);          \
        float2 p1 = __half22float2(*(((const __half2*)&(F).x) + 1));  \
        float2 p2 = __half22float2(*(const __half2*)&(F).z);          \
        float2 p3 = __half22float2(*(((const __half2*)&(F).z) + 1));  \
        acc[0] += (W) * p0.x;  acc[1] += (W) * p0.y;                  \
        acc[2] += (W) * p1.x;  acc[3] += (W) * p1.y;                  \
        acc[4] += (W) * p2.x;  acc[5] += (W) * p2.y;                  \
        acc[6] += (W) * p3.x;  acc[7] += (W) * p3.y;                  \
        wsum += (W);                                                  \
    } while (0)

        ACCUM(f0, w0);
        ACCUM(f1, w1);
        ACCUM(f2, w2);
        ACCUM(f3, w3);
    }
    for (; j < end; j++) {
        int dst = __ldg(&g_cdst[j]);
        float w = __ldg(&g_w[(size_t)j * 4 + h]);
        uint4 f = __ldg(fp + (size_t)dst * 32 + l);
        ACCUM(f, w);
    }
#undef ACCUM

    float inv = 1.0f / wsum;     // 0 edges -> inf -> 0*inf = NaN, matching reference
    float4 o0 = make_float4(acc[0] * inv, acc[1] * inv, acc[2] * inv, acc[3] * inv);
    float4 o1 = make_float4(acc[4] * inv, acc[5] * inv, acc[6] * inv, acc[7] * inv);
    float* op = out + (size_t)n * CO + l * 8;
    *(float4*)(op)     = o0;
    *(float4*)(op + 4) = o1;
}

extern "C" void kernel_launch(void* const* d_in, const int* in_sizes, int n_in,
                              void* d_out, int out_size) {
    const float* x    = (const float*)d_in[0];
    const int*   idx  = (const int*)d_in[1];
    const float* elem = (const float*)d_in[2];
    const float* Ws   = (const float*)d_in[3];
    const float* bs   = (const float*)d_in[4];
    const float* aw   = (const float*)d_in[5];
    const float* ab   = (const float*)d_in[6];
    float* out = (float*)d_out;

    static cudaStream_t s1 = nullptr;
    static cudaEvent_t evF = nullptr, evScan = nullptr;
    if (!s1) {   // created on the (uncaptured) correctness call, reused thereafter
        cudaStreamCreateWithFlags(&s1, cudaStreamNonBlocking);
        cudaEventCreateWithFlags(&evF, cudaEventDisableTiming);
        cudaEventCreateWithFlags(&evScan, cudaEventDisableTiming);
    }

    // fork from origin (legacy) stream
    cudaEventRecord(evF, 0);
    cudaStreamWaitEvent(s1, evF, 0);

    // s1: CSR chain
    zero_kernel<<<(NN + 255) / 256, 256, 0, s1>>>();
    count_kernel<<<(NE + 255) / 256, 256, 0, s1>>>(idx);
    scan1_kernel<<<NB_SCAN, 256, 0, s1>>>();
    scan2_kernel<<<1, 256, 0, s1>>>();
    scan3_kernel<<<NB_SCAN, 256, 0, s1>>>();
    cudaEventRecord(evScan, s1);

    // legacy: GEMM chain (produces feats + a_s/a_d)
    prep_kernel<<<1, 256>>>(bs);
    prepB_kernel<<<(CO * DI + 255) / 256, 256>>>(Ws);
    gemm_mma_kernel<<<dim3(2, (NN + 127) / 128), 256>>>(x, aw);

    // legacy: place needs gemm (same stream) + scan (cross-stream)
    cudaStreamWaitEvent(0, evScan, 0);
    place_kernel<<<(NE + 255) / 256, 256>>>(idx, elem, aw, ab);
    gather_kernel<<<(NN + 7) / 8, 256>>>(out);
}

// round 16
// speedup vs baseline: 1.1417x; 1.0264x over previous
#include <cuda_runtime.h>
#include <cuda_fp16.h>
#include <cstdint>

#define NN 50000
#define NE 800000
#define NH 4
#define DI 256
#define DO 64
#define CO 256   // NH * DO

#define NB_SCAN 196  // ceil(NN/256)

// ---- scratch (device globals; no runtime allocation) ----
// g_deg starts zero-initialized (module load) and is re-zeroed by gather each
// call, so the zero_kernel is not needed.
__device__ __half g_featsh[NN * CO];     // [n][h*64+o] fp16
__device__ float g_as[NN * NH];          // per-node src dots (written by gemm epilogue)
__device__ float g_ad[NN * NH];          // per-node dst dots
__device__ float g_w[NE * NH];           // CSR-ordered weights [pos][h]
__device__ int   g_rank[NE];             // rank of edge within its src bucket
__device__ int   g_cdst[NE];
__device__ int   g_deg[NN];
__device__ int   g_rowstart[NN + 1];
__device__ float g_bcat[CO];
__device__ int   g_part[NB_SCAN];
__device__ __half g_Bh[CO * DI];         // Bt[n][k] fp16  (n = h*64+o, k = d)

// ==================== small prep kernels ====================
__global__ void prep_kernel(const float* __restrict__ bs) {
    int i = blockIdx.x * blockDim.x + threadIdx.x;
    if (i < CO) {
        int h = i >> 6, o = i & 63;
        g_bcat[i] = bs[h * DO + o];
    }
}

// B transposed fp16: Bt[n][k] = Ws[h][k][o], n = h*64+o
__global__ void prepB_kernel(const float* __restrict__ Ws) {
    int i = blockIdx.x * blockDim.x + threadIdx.x;
    if (i >= CO * DI) return;
    int n = i >> 8, k = i & 255;
    int h = n >> 6, o = n & 63;
    g_Bh[i] = __float2half(Ws[(h * DI + k) * DO + o]);
}

// count + capture per-edge rank (atomicAdd return value)
__global__ void count_kernel(const int* __restrict__ idx) {
    int e = blockIdx.x * blockDim.x + threadIdx.x;
    if (e < NE) g_rank[e] = atomicAdd(&g_deg[idx[e]], 1);
}

// ---------------- 2-phase scan (scan2 folded into scan3) ----------------
__global__ void scan1_kernel() {
    __shared__ int sd[256];
    int tid = threadIdx.x;
    int i = blockIdx.x * 256 + tid;
    sd[tid] = (i < NN) ? g_deg[i] : 0;
    __syncthreads();
    for (int off = 128; off; off >>= 1) {
        if (tid < off) sd[tid] += sd[tid + off];
        __syncthreads();
    }
    if (tid == 0) g_part[blockIdx.x] = sd[0];
}

__global__ void scan3_kernel() {
    __shared__ int sp[256];   // inclusive scan of block sums
    __shared__ int sd[256];
    int tid = threadIdx.x;
    int b = blockIdx.x;
    // scan the 196 partial sums (every block redundantly; cheap)
    int pv = (tid < NB_SCAN) ? g_part[tid] : 0;
    sp[tid] = pv;
    __syncthreads();
    for (int off = 1; off < 256; off <<= 1) {
        int t = (tid >= off) ? sp[tid - off] : 0;
        __syncthreads();
        sp[tid] += t;
        __syncthreads();
    }
    int base = (b > 0) ? sp[b - 1] : 0;
    // local exclusive scan of deg
    int i = b * 256 + tid;
    int v = (i < NN) ? g_deg[i] : 0;
    sd[tid] = v;
    __syncthreads();
    for (int off = 1; off < 256; off <<= 1) {
        int t = (tid >= off) ? sd[tid - off] : 0;
        __syncthreads();
        sd[tid] += t;
        __syncthreads();
    }
    if (i < NN) g_rowstart[i] = base + sd[tid] - v;
    if (b == NB_SCAN - 1 && tid == 0) g_rowstart[NN] = sp[NB_SCAN - 1];
}

// ==================== warp-level fp16 MMA GEMM + fused attention dots ====================
// 512 threads, 16 warps: full 128(M) x 256(N) tile per block -> x read/converted ONCE
#define KS 32          // k-chunk
#define LDA 40         // smem row stride in half elements

__device__ __forceinline__ void mma_f16(float* c, const uint32_t* a, const uint32_t* b) {
    asm volatile(
        "mma.sync.aligned.m16n8k16.row.col.f32.f16.f16.f32 "
        "{%0,%1,%2,%3}, {%4,%5,%6,%7}, {%8,%9}, {%0,%1,%2,%3};"
        : "+f"(c[0]), "+f"(c[1]), "+f"(c[2]), "+f"(c[3])
        : "r"(a[0]), "r"(a[1]), "r"(a[2]), "r"(a[3]), "r"(b[0]), "r"(b[1]));
}

__global__ void __launch_bounds__(512, 1) gemm_mma_kernel(const float* __restrict__ x,
                                                          const float* __restrict__ aw) {
    __shared__ __align__(16) __half sAh[128 * LDA];
    __shared__ __align__(16) __half sBh[256 * LDA];

    int tid = threadIdx.x;
    int wid = tid >> 5;
    int lane = tid & 31;
    int group = lane >> 2;
    int tid4 = lane & 3;
    int bm = blockIdx.x * 128;
    int wm = (wid & 3) * 32;        // 4 M-tiles
    int wn = (wid >> 2) * 64;       // 4 N-tiles (heads)

    // A load mapping: 512 thr, 8 halves each per chunk
    int lrowA = tid >> 2;           // 0..127
    int lkA = (tid & 3) * 8;        // 0,8,16,24
    int growA = bm + lrowA;
    bool aok = growA < NN;
    const float4* xp = (const float4*)(x + (size_t)growA * DI);

    // B load mapping: 512 thr, 16 halves each per chunk (256 rows)
    int lrowB = tid >> 1;           // 0..255
    int lkB = (tid & 1) * 16;
    const uint4* bhp = (const uint4*)(g_Bh + (size_t)lrowB * DI);

    float acc[2][8][4] = {};

    for (int c = 0; c < DI / KS; c++) {
        if (c) __syncthreads();
        int ck = c * KS;
        // ---- A: fp32 -> fp16 into smem (once per row) ----
#pragma unroll
        for (int q = 0; q < 2; q++) {
            float4 v = aok ? __ldg(xp + ((ck + lkA) >> 2) + q)
                           : make_float4(0.f, 0.f, 0.f, 0.f);
            __half2 h01 = __floats2half2_rn(v.x, v.y);
            __half2 h23 = __floats2half2_rn(v.z, v.w);
            int e = lrowA * LDA + lkA + q * 4;
            *(__half2*)&sAh[e]     = h01;
            *(__half2*)&sAh[e + 2] = h23;
        }
        // ---- B: pre-converted fp16 into smem ----
        {
            uint4 v0 = __ldg(bhp + ((ck + lkB) >> 3));
            uint4 v1 = __ldg(bhp + ((ck + lkB) >> 3) + 1);
            int e = lrowB * LDA + lkB;
            *(uint4*)&sBh[e]     = v0;
            *(uint4*)&sBh[e + 8] = v1;
        }
        __syncthreads();

        // ---- compute: 2 k16 steps ----
#pragma unroll
        for (int k16 = 0; k16 < KS; k16 += 16) {
            uint32_t ah[2][4];
#pragma unroll
            for (int mi = 0; mi < 2; mi++) {
                int r0 = (wm + mi * 16 + group) * LDA + k16 + tid4 * 2;
                ah[mi][0] = *(const uint32_t*)&sAh[r0];
                ah[mi][1] = *(const uint32_t*)&sAh[r0 + 8 * LDA];
                ah[mi][2] = *(const uint32_t*)&sAh[r0 + 8];
                ah[mi][3] = *(const uint32_t*)&sAh[r0 + 8 * LDA + 8];
            }
#pragma unroll
            for (int ni = 0; ni < 8; ni++) {
                int rb = (wn + ni * 8 + group) * LDA + k16 + tid4 * 2;
                uint32_t bh[2];
                bh[0] = *(const uint32_t*)&sBh[rb];
                bh[1] = *(const uint32_t*)&sBh[rb + 8];
#pragma unroll
                for (int mi = 0; mi < 2; mi++)
                    mma_f16(acc[mi][ni], ah[mi], bh);
            }
        }
    }

    // ---- epilogue: bias, fp16 store, fused a_s/a_d dots ----
    int hh = wn >> 6;               // unique head per warp
    const float* awh = aw + hh * (2 * DO + 1);

    float ps[2][2] = {};
    float pd[2][2] = {};

#pragma unroll
    for (int ni = 0; ni < 8; ni++) {
        int o = ni * 8 + tid4 * 2;          // col within 64-col head block
        int col = wn + o;
        float2 bb = *(const float2*)(g_bcat + col);
        float aws0 = __ldg(&awh[o]);
        float aws1 = __ldg(&awh[o + 1]);
        float awd0 = __ldg(&awh[DO + o]);
        float awd1 = __ldg(&awh[DO + o + 1]);
#pragma unroll
        for (int mi = 0; mi < 2; mi++) {
            int row0 = bm + wm + mi * 16 + group;
            int row1 = row0 + 8;
            float v00 = acc[mi][ni][0] + bb.x;
            float v01 = acc[mi][ni][1] + bb.y;
            float v10 = acc[mi][ni][2] + bb.x;
            float v11 = acc[mi][ni][3] + bb.y;
            ps[mi][0] += v00 * aws0 + v01 * aws1;
            pd[mi][0] += v00 * awd0 + v01 * awd1;
            ps[mi][1] += v10 * aws0 + v11 * aws1;
            pd[mi][1] += v10 * awd0 + v11 * awd1;
            if (row0 < NN)
                *(__half2*)(g_featsh + (size_t)row0 * CO + col) = __floats2half2_rn(v00, v01);
            if (row1 < NN)
                *(__half2*)(g_featsh + (size_t)row1 * CO + col) = __floats2half2_rn(v10, v11);
        }
    }

    // quad reduction over tid4
#pragma unroll
    for (int mi = 0; mi < 2; mi++)
#pragma unroll
        for (int r = 0; r < 2; r++) {
            ps[mi][r] += __shfl_xor_sync(0xffffffffu, ps[mi][r], 1);
            ps[mi][r] += __shfl_xor_sync(0xffffffffu, ps[mi][r], 2);
            pd[mi][r] += __shfl_xor_sync(0xffffffffu, pd[mi][r], 1);
            pd[mi][r] += __shfl_xor_sync(0xffffffffu, pd[mi][r], 2);
        }
    if (tid4 == 0) {
#pragma unroll
        for (int mi = 0; mi < 2; mi++)
#pragma unroll
            for (int r = 0; r < 2; r++) {
                int row = bm + wm + mi * 16 + group + r * 8;
                if (row < NN) {
                    g_as[row * NH + hh] = ps[mi][r];
                    g_ad[row * NH + hh] = pd[mi][r];
                }
            }
    }
}

// ---------------- fused: edge weights + CSR placement (no atomics) ----------------
__global__ void place_kernel(const int* __restrict__ idx, const float* __restrict__ elem,
                             const float* __restrict__ aw, const float* __restrict__ ab) {
    int e = blockIdx.x * blockDim.x + threadIdx.x;
    if (e >= NE) return;
    int s = idx[e];
    int d = idx[NE + e];
    float el = elem[e];
    float4 as = *(const float4*)(g_as + s * NH);
    float4 ad = *(const float4*)(g_ad + d * NH);
    const float* asv = (const float*)&as;
    const float* adv = (const float*)&ad;
    float w[NH];
#pragma unroll
    for (int h = 0; h < NH; h++) {
        float sc = asv[h] + adv[h]
                 + __ldg(&aw[h * (2 * DO + 1) + 2 * DO]) * el + __ldg(&ab[h]);
        sc = sc * (1.0f / 20.0f);
        w[h] = __expf(-fmaxf(sc, 0.0f));
    }
    int pos = g_rowstart[s] + g_rank[e];
    g_cdst[pos] = d;
    *(float4*)(g_w + (size_t)pos * 4) = make_float4(w[0], w[1], w[2], w[3]);
}

// ---------------- per-node gather + normalize (32 thr/node, 8 nodes/block) ----------------
__global__ void __launch_bounds__(256) gather_kernel(float* __restrict__ out) {
    int t = threadIdx.x;
    int n = blockIdx.x * 8 + (t >> 5);
    int l = t & 31;              // lane handles elements l*8 .. l*8+7
    int h = l >> 3;              // head index = (l*8)/64
    int start = g_rowstart[n];
    int end = g_rowstart[n + 1];

    const uint4* fp = (const uint4*)g_featsh;   // 32 uint4 per row (256 half)
    float acc[8] = {};
    float wsum = 0.f;

    int j = start;
    for (; j + 4 <= end; j += 4) {
        int d0 = __ldg(&g_cdst[j + 0]);
        int d1 = __ldg(&g_cdst[j + 1]);
        int d2 = __ldg(&g_cdst[j + 2]);
        int d3 = __ldg(&g_cdst[j + 3]);
        float w0 = __ldg(&g_w[(size_t)(j + 0) * 4 + h]);
        float w1 = __ldg(&g_w[(size_t)(j + 1) * 4 + h]);
        float w2 = __ldg(&g_w[(size_t)(j + 2) * 4 + h]);
        float w3 = __ldg(&g_w[(size_t)(j + 3) * 4 + h]);
        uint4 f0 = __ldg(fp + (size_t)d0 * 32 + l);
        uint4 f1 = __ldg(fp + (size_t)d1 * 32 + l);
        uint4 f2 = __ldg(fp + (size_t)d2 * 32 + l);
        uint4 f3 = __ldg(fp + (size_t)d3 * 32 + l);

#define ACCUM(F, W) do {                                              \
        float2 p0 = __half22float2(*(const __half2*)&(F).x);          \
        float2 p1 = __half22float2(*(((const __half2*)&(F).x) + 1));  \
        float2 p2 = __half22float2(*(const __half2*)&(F).z);          \
        float2 p3 = __half22float2(*(((const __half2*)&(F).z) + 1));  \
        acc[0] += (W) * p0.x;  acc[1] += (W) * p0.y;                  \
        acc[2] += (W) * p1.x;  acc[3] += (W) * p1.y;                  \
        acc[4] += (W) * p2.x;  acc[5] += (W) * p2.y;                  \
        acc[6] += (W) * p3.x;  acc[7] += (W) * p3.y;                  \
        wsum += (W);                                                  \
    } while (0)

        ACCUM(f0, w0);
        ACCUM(f1, w1);
        ACCUM(f2, w2);
        ACCUM(f3, w3);
    }
    for (; j < end; j++) {
        int dst = __ldg(&g_cdst[j]);
        float w = __ldg(&g_w[(size_t)j * 4 + h]);
        uint4 f = __ldg(fp + (size_t)dst * 32 + l);
        ACCUM(f, w);
    }
#undef ACCUM

    float inv = 1.0f / wsum;     // 0 edges -> inf -> 0*inf = NaN, matching reference
    float4 o0 = make_float4(acc[0] * inv, acc[1] * inv, acc[2] * inv, acc[3] * inv);
    float4 o1 = make_float4(acc[4] * inv, acc[5] * inv, acc[6] * inv, acc[7] * inv);
    float* op = out + (size_t)n * CO + l * 8;
    *(float4*)(op)     = o0;
    *(float4*)(op + 4) = o1;

    // maintain invariant: deg is zero at entry of every call (zero_kernel deleted)
    if (l == 0) g_deg[n] = 0;
}

extern "C" void kernel_launch(void* const* d_in, const int* in_sizes, int n_in,
                              void* d_out, int out_size) {
    const float* x    = (const float*)d_in[0];
    const int*   idx  = (const int*)d_in[1];
    const float* elem = (const float*)d_in[2];
    const float* Ws   = (const float*)d_in[3];
    const float* bs   = (const float*)d_in[4];
    const float* aw   = (const float*)d_in[5];
    const float* ab   = (const float*)d_in[6];
    float* out = (float*)d_out;

    static cudaStream_t s1 = nullptr;
    static cudaEvent_t evF = nullptr, evScan = nullptr;
    if (!s1) {   // created on the (uncaptured) correctness call, reused thereafter
        cudaStreamCreateWithFlags(&s1, cudaStreamNonBlocking);
        cudaEventCreateWithFlags(&evF, cudaEventDisableTiming);
        cudaEventCreateWithFlags(&evScan, cudaEventDisableTiming);
    }

    // fork from origin (legacy) stream
    cudaEventRecord(evF, 0);
    cudaStreamWaitEvent(s1, evF, 0);

    // s1: CSR chain (deg already zero: init-time zeros on call 1, gather re-zeroes after)
    count_kernel<<<(NE + 255) / 256, 256, 0, s1>>>(idx);
    scan1_kernel<<<NB_SCAN, 256, 0, s1>>>();
    scan3_kernel<<<NB_SCAN, 256, 0, s1>>>();
    cudaEventRecord(evScan, s1);

    // legacy: GEMM chain (produces feats + a_s/a_d)
    prep_kernel<<<1, 256>>>(bs);
    prepB_kernel<<<(CO * DI + 255) / 256, 256>>>(Ws);
    gemm_mma_kernel<<<(NN + 127) / 128, 512>>>(x, aw);

    // legacy: place needs gemm (same stream) + scan (cross-stream)
    cudaStreamWaitEvent(0, evScan, 0);
    place_kernel<<<(NE + 255) / 256, 256>>>(idx, elem, aw, ab);
    gather_kernel<<<(NN + 7) / 8, 256>>>(out);
}

// round 17
// speedup vs baseline: 1.2750x; 1.1167x over previous
#include <cuda_runtime.h>
#include <cuda_fp16.h>
#include <cstdint>

#define NN 50000
#define NE 800000
#define NH 4
#define DI 256
#define DO 64
#define CO 256   // NH * DO

#define NB_SCAN 196  // ceil(NN/256)

// ---- scratch (device globals; no runtime allocation) ----
// g_deg starts zero-initialized (module load) and is re-zeroed by gather each
// call, so no zero kernel is needed.
__device__ __half g_featsh[NN * CO];     // [n][h*64+o] fp16
__device__ float g_as[NN * NH];          // per-node src dots (written by gemm epilogue)
__device__ float g_ad[NN * NH];          // per-node dst dots
__device__ float g_w[NE * NH];           // CSR-ordered weights [pos][h]
__device__ int   g_rank[NE];             // rank of edge within its src bucket
__device__ int   g_cdst[NE];
__device__ int   g_deg[NN];
__device__ int   g_rowstart[NN + 1];
__device__ float g_bcat[CO];
__device__ int   g_part[NB_SCAN];
__device__ __half g_Bh[CO * DI];         // Bt[n][k] fp16  (n = h*64+o, k = d)

// ==================== prep: B transpose->fp16 + bcat (single launch) ====================
__global__ void prepB_kernel(const float* __restrict__ Ws, const float* __restrict__ bs) {
    int i = blockIdx.x * blockDim.x + threadIdx.x;
    if (i < CO * DI) {
        int n = i >> 8, k = i & 255;
        int h = n >> 6, o = n & 63;
        g_Bh[i] = __float2half(Ws[(h * DI + k) * DO + o]);
    }
    if (i < CO) {
        int h = i >> 6, o = i & 63;
        g_bcat[i] = bs[h * DO + o];
    }
}

// count + capture per-edge rank (atomicAdd return value)
__global__ void count_kernel(const int* __restrict__ idx) {
    int e = blockIdx.x * blockDim.x + threadIdx.x;
    if (e < NE) g_rank[e] = atomicAdd(&g_deg[idx[e]], 1);
}

// ---------------- 2-phase scan ----------------
__global__ void scan1_kernel() {
    __shared__ int sd[256];
    int tid = threadIdx.x;
    int i = blockIdx.x * 256 + tid;
    sd[tid] = (i < NN) ? g_deg[i] : 0;
    __syncthreads();
    for (int off = 128; off; off >>= 1) {
        if (tid < off) sd[tid] += sd[tid + off];
        __syncthreads();
    }
    if (tid == 0) g_part[blockIdx.x] = sd[0];
}

__global__ void scan3_kernel() {
    __shared__ int sp[256];   // inclusive scan of block sums
    __shared__ int sd[256];
    int tid = threadIdx.x;
    int b = blockIdx.x;
    int pv = (tid < NB_SCAN) ? g_part[tid] : 0;
    sp[tid] = pv;
    __syncthreads();
    for (int off = 1; off < 256; off <<= 1) {
        int t = (tid >= off) ? sp[tid - off] : 0;
        __syncthreads();
        sp[tid] += t;
        __syncthreads();
    }
    int base = (b > 0) ? sp[b - 1] : 0;
    int i = b * 256 + tid;
    int v = (i < NN) ? g_deg[i] : 0;
    sd[tid] = v;
    __syncthreads();
    for (int off = 1; off < 256; off <<= 1) {
        int t = (tid >= off) ? sd[tid - off] : 0;
        __syncthreads();
        sd[tid] += t;
        __syncthreads();
    }
    if (i < NN) g_rowstart[i] = base + sd[tid] - v;
    if (b == NB_SCAN - 1 && tid == 0) g_rowstart[NN] = sp[NB_SCAN - 1];
}

// ==================== warp-level fp16 MMA GEMM + fused attention dots ====================
// 512 threads, 16 warps: full 128(M) x 256(N) tile; register-prefetch pipeline
#define KS 32          // k-chunk
#define LDA 40         // smem row stride in half elements

__device__ __forceinline__ void mma_f16(float* c, const uint32_t* a, const uint32_t* b) {
    asm volatile(
        "mma.sync.aligned.m16n8k16.row.col.f32.f16.f16.f32 "
        "{%0,%1,%2,%3}, {%4,%5,%6,%7}, {%8,%9}, {%0,%1,%2,%3};"
        : "+f"(c[0]), "+f"(c[1]), "+f"(c[2]), "+f"(c[3])
        : "r"(a[0]), "r"(a[1]), "r"(a[2]), "r"(a[3]), "r"(b[0]), "r"(b[1]));
}

__global__ void __launch_bounds__(512, 1) gemm_mma_kernel(const float* __restrict__ x,
                                                          const float* __restrict__ aw) {
    __shared__ __align__(16) __half sAh[128 * LDA];
    __shared__ __align__(16) __half sBh[256 * LDA];

    int tid = threadIdx.x;
    int wid = tid >> 5;
    int lane = tid & 31;
    int group = lane >> 2;
    int tid4 = lane & 3;
    int bm = blockIdx.x * 128;
    int wm = (wid & 3) * 32;        // 4 M-tiles
    int wn = (wid >> 2) * 64;       // 4 N-tiles (heads)

    // A load mapping: 512 thr, 8 halves each per chunk
    int lrowA = tid >> 2;           // 0..127
    int lkA = (tid & 3) * 8;        // 0,8,16,24
    int growA = bm + lrowA;
    bool aok = growA < NN;
    const float4* xp = (const float4*)(x + (size_t)growA * DI);

    // B load mapping: 512 thr, 16 halves each per chunk (256 rows)
    int lrowB = tid >> 1;           // 0..255
    int lkB = (tid & 1) * 16;
    const uint4* bhp = (const uint4*)(g_Bh + (size_t)lrowB * DI);

    float acc[2][8][4] = {};

    // prefetch registers
    float4 va[2];
    uint4 vb[2];

    // ---- preload chunk 0 ----
#pragma unroll
    for (int q = 0; q < 2; q++)
        va[q] = aok ? __ldg(xp + (lkA >> 2) + q) : make_float4(0.f, 0.f, 0.f, 0.f);
    vb[0] = __ldg(bhp + (lkB >> 3));
    vb[1] = __ldg(bhp + (lkB >> 3) + 1);
    {
#pragma unroll
        for (int q = 0; q < 2; q++) {
            int e = lrowA * LDA + lkA + q * 4;
            *(__half2*)&sAh[e]     = __floats2half2_rn(va[q].x, va[q].y);
            *(__half2*)&sAh[e + 2] = __floats2half2_rn(va[q].z, va[q].w);
        }
        int e = lrowB * LDA + lkB;
        *(uint4*)&sBh[e]     = vb[0];
        *(uint4*)&sBh[e + 8] = vb[1];
    }
    __syncthreads();

    for (int c = 0; c < DI / KS; c++) {
        // ---- issue next chunk's global loads early (hide latency under mma) ----
        if (c + 1 < DI / KS) {
            int ck = (c + 1) * KS;
#pragma unroll
            for (int q = 0; q < 2; q++)
                va[q] = aok ? __ldg(xp + ((ck + lkA) >> 2) + q)
                            : make_float4(0.f, 0.f, 0.f, 0.f);
            vb[0] = __ldg(bhp + ((ck + lkB) >> 3));
            vb[1] = __ldg(bhp + ((ck + lkB) >> 3) + 1);
        }

        // ---- compute current chunk from smem ----
#pragma unroll
        for (int k16 = 0; k16 < KS; k16 += 16) {
            uint32_t ah[2][4];
#pragma unroll
            for (int mi = 0; mi < 2; mi++) {
                int r0 = (wm + mi * 16 + group) * LDA + k16 + tid4 * 2;
                ah[mi][0] = *(const uint32_t*)&sAh[r0];
                ah[mi][1] = *(const uint32_t*)&sAh[r0 + 8 * LDA];
                ah[mi][2] = *(const uint32_t*)&sAh[r0 + 8];
                ah[mi][3] = *(const uint32_t*)&sAh[r0 + 8 * LDA + 8];
            }
#pragma unroll
            for (int ni = 0; ni < 8; ni++) {
                int rb = (wn + ni * 8 + group) * LDA + k16 + tid4 * 2;
                uint32_t bh[2];
                bh[0] = *(const uint32_t*)&sBh[rb];
                bh[1] = *(const uint32_t*)&sBh[rb + 8];
#pragma unroll
                for (int mi = 0; mi < 2; mi++)
                    mma_f16(acc[mi][ni], ah[mi], bh);
            }
        }

        // ---- store prefetched chunk into smem ----
        if (c + 1 < DI / KS) {
            __syncthreads();   // everyone done computing current chunk
#pragma unroll
            for (int q = 0; q < 2; q++) {
                int e = lrowA * LDA + lkA + q * 4;
                *(__half2*)&sAh[e]     = __floats2half2_rn(va[q].x, va[q].y);
                *(__half2*)&sAh[e + 2] = __floats2half2_rn(va[q].z, va[q].w);
            }
            int e = lrowB * LDA + lkB;
            *(uint4*)&sBh[e]     = vb[0];
            *(uint4*)&sBh[e + 8] = vb[1];
            __syncthreads();   // stores visible
        }
    }

    // ---- epilogue: bias, fp16 store, fused a_s/a_d dots ----
    int hh = wn >> 6;               // unique head per warp
    const float* awh = aw + hh * (2 * DO + 1);

    float ps[2][2] = {};
    float pd[2][2] = {};

#pragma unroll
    for (int ni = 0; ni < 8; ni++) {
        int o = ni * 8 + tid4 * 2;          // col within 64-col head block
        int col = wn + o;
        float2 bb = *(const float2*)(g_bcat + col);
        float aws0 = __ldg(&awh[o]);
        float aws1 = __ldg(&awh[o + 1]);
        float awd0 = __ldg(&awh[DO + o]);
        float awd1 = __ldg(&awh[DO + o + 1]);
#pragma unroll
        for (int mi = 0; mi < 2; mi++) {
            int row0 = bm + wm + mi * 16 + group;
            int row1 = row0 + 8;
            float v00 = acc[mi][ni][0] + bb.x;
            float v01 = acc[mi][ni][1] + bb.y;
            float v10 = acc[mi][ni][2] + bb.x;
            float v11 = acc[mi][ni][3] + bb.y;
            ps[mi][0] += v00 * aws0 + v01 * aws1;
            pd[mi][0] += v00 * awd0 + v01 * awd1;
            ps[mi][1] += v10 * aws0 + v11 * aws1;
            pd[mi][1] += v10 * awd0 + v11 * awd1;
            if (row0 < NN)
                *(__half2*)(g_featsh + (size_t)row0 * CO + col) = __floats2half2_rn(v00, v01);
            if (row1 < NN)
                *(__half2*)(g_featsh + (size_t)row1 * CO + col) = __floats2half2_rn(v10, v11);
        }
    }

    // quad reduction over tid4
#pragma unroll
    for (int mi = 0; mi < 2; mi++)
#pragma unroll
        for (int r = 0; r < 2; r++) {
            ps[mi][r] += __shfl_xor_sync(0xffffffffu, ps[mi][r], 1);
            ps[mi][r] += __shfl_xor_sync(0xffffffffu, ps[mi][r], 2);
            pd[mi][r] += __shfl_xor_sync(0xffffffffu, pd[mi][r], 1);
            pd[mi][r] += __shfl_xor_sync(0xffffffffu, pd[mi][r], 2);
        }
    if (tid4 == 0) {
#pragma unroll
        for (int mi = 0; mi < 2; mi++)
#pragma unroll
            for (int r = 0; r < 2; r++) {
                int row = bm + wm + mi * 16 + group + r * 8;
                if (row < NN) {
                    g_as[row * NH + hh] = ps[mi][r];
                    g_ad[row * NH + hh] = pd[mi][r];
                }
            }
    }
}

// ---------------- fused: edge weights + CSR placement (no atomics) ----------------
__global__ void place_kernel(const int* __restrict__ idx, const float* __restrict__ elem,
                             const float* __restrict__ aw, const float* __restrict__ ab) {
    int e = blockIdx.x * blockDim.x + threadIdx.x;
    if (e >= NE) return;
    int s = idx[e];
    int d = idx[NE + e];
    float el = elem[e];
    float4 as = *(const float4*)(g_as + s * NH);
    float4 ad = *(const float4*)(g_ad + d * NH);
    const float* asv = (const float*)&as;
    const float* adv = (const float*)&ad;
    float w[NH];
#pragma unroll
    for (int h = 0; h < NH; h++) {
        float sc = asv[h] + adv[h]
                 + __ldg(&aw[h * (2 * DO + 1) + 2 * DO]) * el + __ldg(&ab[h]);
        sc = sc * (1.0f / 20.0f);
        w[h] = __expf(-fmaxf(sc, 0.0f));
    }
    int pos = g_rowstart[s] + g_rank[e];
    g_cdst[pos] = d;
    *(float4*)(g_w + (size_t)pos * 4) = make_float4(w[0], w[1], w[2], w[3]);
}

// ---------------- per-node gather + normalize (32 thr/node, 8 nodes/block) ----------------
__global__ void __launch_bounds__(256) gather_kernel(float* __restrict__ out) {
    int t = threadIdx.x;
    int n = blockIdx.x * 8 + (t >> 5);
    int l = t & 31;              // lane handles elements l*8 .. l*8+7
    int h = l >> 3;              // head index = (l*8)/64
    int start = g_rowstart[n];
    int end = g_rowstart[n + 1];

    const uint4* fp = (const uint4*)g_featsh;   // 32 uint4 per row (256 half)
    float acc[8] = {};
    float wsum = 0.f;

    int j = start;
    for (; j + 4 <= end; j += 4) {
        int d0 = __ldg(&g_cdst[j + 0]);
        int d1 = __ldg(&g_cdst[j + 1]);
        int d2 = __ldg(&g_cdst[j + 2]);
        int d3 = __ldg(&g_cdst[j + 3]);
        float w0 = __ldg(&g_w[(size_t)(j + 0) * 4 + h]);
        float w1 = __ldg(&g_w[(size_t)(j + 1) * 4 + h]);
        float w2 = __ldg(&g_w[(size_t)(j + 2) * 4 + h]);
        float w3 = __ldg(&g_w[(size_t)(j + 3) * 4 + h]);
        uint4 f0 = __ldg(fp + (size_t)d0 * 32 + l);
        uint4 f1 = __ldg(fp + (size_t)d1 * 32 + l);
        uint4 f2 = __ldg(fp + (size_t)d2 * 32 + l);
        uint4 f3 = __ldg(fp + (size_t)d3 * 32 + l);

#define ACCUM(F, W) do {                                              \
        float2 p0 = __half22float2(*(const __half2*)&(F).x);          \
        float2 p1 = __half22float2(*(((const __half2*)&(F).x) + 1));  \
        float2 p2 = __half22float2(*(const __half2*)&(F).z);          \
        float2 p3 = __half22float2(*(((const __half2*)&(F).z) + 1));  \
        acc[0] += (W) * p0.x;  acc[1] += (W) * p0.y;                  \
        acc[2] += (W) * p1.x;  acc[3] += (W) * p1.y;                  \
        acc[4] += (W) * p2.x;  acc[5] += (W) * p2.y;                  \
        acc[6] += (W) * p3.x;  acc[7] += (W) * p3.y;                  \
        wsum += (W);                                                  \
    } while (0)

        ACCUM(f0, w0);
        ACCUM(f1, w1);
        ACCUM(f2, w2);
        ACCUM(f3, w3);
    }
    for (; j < end; j++) {
        int dst = __ldg(&g_cdst[j]);
        float w = __ldg(&g_w[(size_t)j * 4 + h]);
        uint4 f = __ldg(fp + (size_t)dst * 32 + l);
        ACCUM(f, w);
    }
#undef ACCUM

    float inv = 1.0f / wsum;     // 0 edges -> inf -> 0*inf = NaN, matching reference
    float4 o0 = make_float4(acc[0] * inv, acc[1] * inv, acc[2] * inv, acc[3] * inv);
    float4 o1 = make_float4(acc[4] * inv, acc[5] * inv, acc[6] * inv, acc[7] * inv);
    float* op = out + (size_t)n * CO + l * 8;
    *(float4*)(op)     = o0;
    *(float4*)(op + 4) = o1;

    // maintain invariant: deg is zero at entry of every call
    if (l == 0) g_deg[n] = 0;
}

extern "C" void kernel_launch(void* const* d_in, const int* in_sizes, int n_in,
                              void* d_out, int out_size) {
    const float* x    = (const float*)d_in[0];
    const int*   idx  = (const int*)d_in[1];
    const float* elem = (const float*)d_in[2];
    const float* Ws   = (const float*)d_in[3];
    const float* bs   = (const float*)d_in[4];
    const float* aw   = (const float*)d_in[5];
    const float* ab   = (const float*)d_in[6];
    float* out = (float*)d_out;

    static cudaStream_t s1 = nullptr;
    static cudaEvent_t evF = nullptr, evScan = nullptr;
    if (!s1) {   // created on the (uncaptured) correctness call, reused thereafter
        cudaStreamCreateWithFlags(&s1, cudaStreamNonBlocking);
        cudaEventCreateWithFlags(&evF, cudaEventDisableTiming);
        cudaEventCreateWithFlags(&evScan, cudaEventDisableTiming);
    }

    // fork from origin (legacy) stream
    cudaEventRecord(evF, 0);
    cudaStreamWaitEvent(s1, evF, 0);

    // s1: CSR chain (deg already zero: module init on call 1, gather re-zeroes after)
    count_kernel<<<(NE + 255) / 256, 256, 0, s1>>>(idx);
    scan1_kernel<<<NB_SCAN, 256, 0, s1>>>();
    scan3_kernel<<<NB_SCAN, 256, 0, s1>>>();
    cudaEventRecord(evScan, s1);

    // legacy: GEMM chain (produces feats + a_s/a_d)
    prepB_kernel<<<(CO * DI + 255) / 256, 256>>>(Ws, bs);
    gemm_mma_kernel<<<(NN + 127) / 128, 512>>>(x, aw);

    // legacy: place needs gemm (same stream) + scan (cross-stream)
    cudaStreamWaitEvent(0, evScan, 0);
    place_kernel<<<(NE + 255) / 256, 256>>>(idx, elem, aw, ab);
    gather_kernel<<<(NN + 7) / 8, 256>>>(out);
}